// round 11
// baseline (speedup 1.0000x reference)
#include <cuda_runtime.h>
#include <cuda_fp16.h>
#include <cstdint>
#include <math.h>

// ---------------------------------------------------------------------------
// Problem constants
// ---------------------------------------------------------------------------
#define NROWS     8192     // rows in z_i (and z_j)
#define DIM       512      // feature dim
#define BROWS     16384    // combined B rows (zi ++ zj)

#define BM        128      // CTA tile M
#define BN        128      // CTA tile N

// Both paths use 128-byte K-rows per stage chunk:
//   s8  : 128 s8 elems/chunk-row,  CHUNKS8  = 4
//   fp16:  64 f16 elems/chunk-row, CHUNKS16 = 8
#define CHUNKS8   4
#define CHUNKS16  8
#define STAGES    3

#define CHUNK_A_BYTES (BM * 128)             // 16384
#define CHUNK_B_BYTES (BN * 128)             // 16384
#define STAGE_BYTES   (CHUNK_A_BYTES + CHUNK_B_BYTES)  // 32768
#define SMEM_TOTAL    (STAGES * STAGE_BYTES)           // 98304 -> 2 CTAs/SM

#define NEG_TILES     4096   // 64 x 64 full tiles zi x zj
#define POS_OFF_TILES 2016   // strictly-lower triangle of 64x64 blocks (zi x zi)
#define INT8_TILES    (NEG_TILES + POS_OFF_TILES)  // 6112
#define DIAG_TILES    64     // diagonal blocks, fp16 path

#define Q_SCALE       127.0f
#define EXP_COEF8     (10.0f / (Q_SCALE * Q_SCALE))   // exponent per s32 count

// ---------------------------------------------------------------------------
// Global scratch (allocation-free rules: __device__ globals)
// ---------------------------------------------------------------------------
__device__ __half  g_z16[(size_t)BROWS * DIM];  // 16 MB normalized fp16
__device__ int8_t  g_z8 [(size_t)BROWS * DIM];  //  8 MB normalized s8 (x127)
__device__ double g_pos;
__device__ double g_neg;
__device__ unsigned int g_done;

// ---------------------------------------------------------------------------
// PTX helpers — sm_75/80-era features only (PTX target is plain sm_103)
// ---------------------------------------------------------------------------
__device__ __forceinline__ uint32_t smem_to_u32(const void* p) {
    uint32_t a;
    asm("{ .reg .u64 t; cvta.to.shared.u64 t, %1; cvt.u32.u64 %0, t; }" : "=r"(a) : "l"(p));
    return a;
}

#define SWZ(off) ((off) ^ (((off) >> 3) & 0x70u))   // SW128 swizzle for 128B rows

__device__ __forceinline__ void cp_async16(uint32_t dst_smem, const void* src) {
    asm volatile("cp.async.cg.shared.global [%0], [%1], 16;" :: "r"(dst_smem), "l"(src));
}
#define CP_ASYNC_COMMIT() asm volatile("cp.async.commit_group;" ::: "memory")
#define CP_ASYNC_WAIT_1() asm volatile("cp.async.wait_group 1;" ::: "memory")
#define CP_ASYNC_WAIT_0() asm volatile("cp.async.wait_group 0;" ::: "memory")

__device__ __forceinline__ void ldmatrix_x4(uint32_t* r, uint32_t addr) {
    asm volatile("ldmatrix.sync.aligned.m8n8.x4.shared.b16 {%0,%1,%2,%3}, [%4];"
                 : "=r"(r[0]), "=r"(r[1]), "=r"(r[2]), "=r"(r[3]) : "r"(addr));
}

// fp16 in / fp16 accum (diag path)
__device__ __forceinline__ void mma_f16(uint32_t* c, const uint32_t* a, uint32_t b0, uint32_t b1) {
    asm volatile(
        "mma.sync.aligned.m16n8k16.row.col.f16.f16.f16.f16 "
        "{%0,%1}, {%2,%3,%4,%5}, {%6,%7}, {%0,%1};"
        : "+r"(c[0]), "+r"(c[1])
        : "r"(a[0]), "r"(a[1]), "r"(a[2]), "r"(a[3]), "r"(b0), "r"(b1));
}

// s8 in / s32 accum (bulk path): K=32 per instruction
__device__ __forceinline__ void mma_s8(int* c, const uint32_t* a, uint32_t b0, uint32_t b1) {
    asm volatile(
        "mma.sync.aligned.m16n8k32.row.col.s32.s8.s8.s32 "
        "{%0,%1,%2,%3}, {%4,%5,%6,%7}, {%8,%9}, {%0,%1,%2,%3};"
        : "+r"(c[0]), "+r"(c[1]), "+r"(c[2]), "+r"(c[3])
        : "r"(a[0]), "r"(a[1]), "r"(a[2]), "r"(a[3]), "r"(b0), "r"(b1));
}

__device__ __forceinline__ int8_t q_s8(float x) {
    int v = __float2int_rn(x);
    v = v > 127 ? 127 : (v < -127 ? -127 : v);
    return (int8_t)v;
}

// ---------------------------------------------------------------------------
// Kernel 1: L2-normalize rows into fp16 g_z16 AND s8 g_z8 (x127 scaled).
// One warp per row, 4 independent float4 loads per lane. Resets accumulators.
// ---------------------------------------------------------------------------
__global__ __launch_bounds__(256) void norm_kernel(const float* __restrict__ zi,
                                                   const float* __restrict__ zj) {
    const int tid  = threadIdx.x;
    const int lane = tid & 31;
    const int row  = blockIdx.x * 8 + (tid >> 5);   // 2048 blocks x 8 warps
    if (blockIdx.x == 0 && tid == 0) { g_pos = 0.0; g_neg = 0.0; g_done = 0u; }

    const float* src = (row < NROWS) ? (zi + (size_t)row * DIM)
                                     : (zj + (size_t)(row - NROWS) * DIM);
    const float4* s4 = reinterpret_cast<const float4*>(src);
    float4 v[4];
    #pragma unroll
    for (int k = 0; k < 4; k++) v[k] = s4[lane + 32 * k];

    float ss = 0.0f;
    #pragma unroll
    for (int k = 0; k < 4; k++)
        ss += v[k].x * v[k].x + v[k].y * v[k].y + v[k].z * v[k].z + v[k].w * v[k].w;
    #pragma unroll
    for (int off = 16; off > 0; off >>= 1)
        ss += __shfl_xor_sync(0xFFFFFFFFu, ss, off);

    float scale = 1.0f / fmaxf(sqrtf(ss), 1e-12f);
    float sq = scale * Q_SCALE;

    __half2*  dst16 = reinterpret_cast<__half2*>(g_z16 + (size_t)row * DIM);
    uint32_t* dst8  = reinterpret_cast<uint32_t*>(g_z8 + (size_t)row * DIM);
    #pragma unroll
    for (int k = 0; k < 4; k++) {
        int e = lane + 32 * k;
        dst16[e * 2 + 0] = __floats2half2_rn(v[k].x * scale, v[k].y * scale);
        dst16[e * 2 + 1] = __floats2half2_rn(v[k].z * scale, v[k].w * scale);
        uint32_t b0 = (uint8_t)q_s8(v[k].x * sq);
        uint32_t b1 = (uint8_t)q_s8(v[k].y * sq);
        uint32_t b2 = (uint8_t)q_s8(v[k].z * sq);
        uint32_t b3 = (uint8_t)q_s8(v[k].w * sq);
        dst8[e] = b0 | (b1 << 8) | (b2 << 16) | (b3 << 24);
    }
}

// ---------------------------------------------------------------------------
// Kernel 2: bulk fused GEMM in s8 IMMA (m16n8k32, s32 accum) + exp-sum
// epilogue. 128x128 tiles, 4 warps (64x64 warp tile), 2 CTAs/SM, register
// double-buffered fragments. Grid = 6112 tiles:
//   idx < 4096 : neg tile: tm = idx&63, B row = NROWS + (idx>>6)*128, w=1
//   idx >= 4096: pos OFF-DIAG: p -> (t,i) with i<t: tm=i, B row = t*128, w=2
// Diagonal pos tiles are handled by the fp16 kernel below.
// ---------------------------------------------------------------------------
__global__ __launch_bounds__(128, 2) void gemm8_kernel() {
    extern __shared__ __align__(1024) char smem[];
    const uint32_t sb = smem_to_u32(smem);
    const int tid   = threadIdx.x;
    const int wid   = tid >> 5;
    const int lane  = tid & 31;
    const int warpM = (wid & 1) * 64;
    const int warpN = (wid >> 1) * 64;

    // ---- tile decode ----
    int tm, rowB;
    float wtile;
    bool is_pos;
    {
        int idx = blockIdx.x;
        if (idx < NEG_TILES) {
            tm    = idx & 63;
            rowB  = NROWS + (idx >> 6) * BN;
            wtile = 1.0f;
            is_pos = false;
        } else {
            int p = idx - NEG_TILES;                    // 0 .. 2015
            int t = (int)((1.0f + sqrtf((float)(8 * p + 1))) * 0.5f);
            while (t * (t + 1) / 2 <= p) t++;
            while (t * (t - 1) / 2 > p) t--;
            int i = p - t * (t - 1) / 2;                // 0 .. t-1 (strictly below diag)
            tm    = i;
            rowB  = t * BN;
            wtile = 2.0f;
            is_pos = true;
        }
    }

    const char* gzA = reinterpret_cast<const char*>(g_z8) + (size_t)tm * BM * DIM;
    const char* gzB = reinterpret_cast<const char*>(g_z8) + (size_t)rowB * DIM;

    int acc[4][8][4];       // s32 accumulators, 128 regs (exact arithmetic)
    #pragma unroll
    for (int i = 0; i < 4; i++)
        #pragma unroll
        for (int j = 0; j < 8; j++)
            #pragma unroll
            for (int k = 0; k < 4; k++) acc[i][j][k] = 0;

    // -------- chunk loader: 16 x cp.async(16B) per thread (A 8 + B 8) --------
    auto load_chunk = [&](int c, int st) {
        uint32_t stA = sb + st * STAGE_BYTES;
        uint32_t stB = stA + CHUNK_A_BYTES;
        const char* srcA = gzA + c * 128;   // 128 bytes of K (=128 s8)
        const char* srcB = gzB + c * 128;
        #pragma unroll
        for (int i = 0; i < 8; i++) {            // A: 1024 16B units / 128 thr
            int u = tid + i * 128;
            int r = u >> 3, c16 = u & 7;
            uint32_t off = (uint32_t)(r * 128 + c16 * 16);
            cp_async16(stA + SWZ(off), srcA + (size_t)r * DIM + c16 * 16);
        }
        #pragma unroll
        for (int i = 0; i < 8; i++) {            // B: 1024 16B units / 128 thr
            int u = tid + i * 128;
            int r = u >> 3, c16 = u & 7;
            uint32_t off = (uint32_t)(r * 128 + c16 * 16);
            cp_async16(stB + SWZ(off), srcB + (size_t)r * DIM + c16 * 16);
        }
        CP_ASYNC_COMMIT();
    };

    // -------- double-buffered fragment registers --------
    // A: 4 mBlocks x 4 regs (16x32 s8), B: 4 ldmatrix.x4 covering 8 nBlocks x 2
    uint32_t af[2][4][4], bf[2][4][4];     // 64 regs

    const int ldRow  = lane & 15;
    const int ldColB = (lane >> 4) << 4;

    auto preload = [&](int st, int ks, int buf) {
        uint32_t stA = sb + st * STAGE_BYTES;
        uint32_t stB = stA + CHUNK_A_BYTES;
        #pragma unroll
        for (int mb = 0; mb < 4; mb++) {
            uint32_t off = (uint32_t)((warpM + mb * 16 + ldRow) * 128 + ks * 32 + ldColB);
            ldmatrix_x4(af[buf][mb], stA + SWZ(off));
        }
        #pragma unroll
        for (int nb = 0; nb < 4; nb++) {
            uint32_t off = (uint32_t)((warpN + nb * 16 + ldRow) * 128 + ks * 32 + ldColB);
            ldmatrix_x4(bf[buf][nb], stB + SWZ(off));
        }
    };

    // 32 IMMAs consuming buffer buf (each b-ldmatrix.x4 feeds 2 n8-fragments)
    auto mma_all = [&](int buf) {
        #pragma unroll
        for (int mb = 0; mb < 4; mb++)
            #pragma unroll
            for (int nb = 0; nb < 4; nb++) {
                mma_s8(acc[mb][nb * 2 + 0], af[buf][mb], bf[buf][nb][0], bf[buf][nb][2]);
                mma_s8(acc[mb][nb * 2 + 1], af[buf][mb], bf[buf][nb][1], bf[buf][nb][3]);
            }
    };

    // -------- prologue --------
    load_chunk(0, 0);
    load_chunk(1, 1);
    CP_ASYNC_WAIT_1();
    __syncthreads();
    preload(0, 0, 0);

    int cur = 0;
    #pragma unroll 1
    for (int c = 0; c < CHUNKS8; c++) {
        const int st = c % STAGES;
        if (c + 2 < CHUNKS8) load_chunk(c + 2, (c + 2) % STAGES);

        #pragma unroll
        for (int ks = 0; ks < 4; ks++) {
            if (ks < 3) preload(st, ks + 1, cur ^ 1);  // hide LDSM under MMAs
            mma_all(cur);
            cur ^= 1;
        }

        if (c + 1 < CHUNKS8) {
            if (c + 2 < CHUNKS8) CP_ASYNC_WAIT_1();
            else                 CP_ASYNC_WAIT_0();
            __syncthreads();
            preload((c + 1) % STAGES, 0, cur);
        }
    }

    // -------- epilogue: weighted sum of exp(EXP_COEF8 * acc) --------
    float lsum = 0.0f;
    #pragma unroll
    for (int i = 0; i < 4; i++)
        #pragma unroll
        for (int j = 0; j < 8; j++)
            #pragma unroll
            for (int k = 0; k < 4; k++)
                lsum += __expf(EXP_COEF8 * (float)acc[i][j][k]);
    lsum *= wtile;

    #pragma unroll
    for (int off = 16; off > 0; off >>= 1)
        lsum += __shfl_xor_sync(0xFFFFFFFFu, lsum, off);

    __shared__ double wsum[4];
    if (lane == 0) wsum[wid] = (double)lsum;
    __syncthreads();
    if (tid == 0) {
        double t = wsum[0] + wsum[1] + wsum[2] + wsum[3];
        atomicAdd(is_pos ? &g_pos : &g_neg, t);
    }
}

// ---------------------------------------------------------------------------
// Kernel 3: diagonal pos tiles (64) in fp16 — exp(10) diagonal dominates
// pos_sum and needs better-than-s8 precision. Last CTA computes the loss.
// ---------------------------------------------------------------------------
__global__ __launch_bounds__(128, 2) void gemm_diag_kernel(float* __restrict__ out) {
    extern __shared__ __align__(1024) char smem[];
    const uint32_t sb = smem_to_u32(smem);
    const int tid   = threadIdx.x;
    const int wid   = tid >> 5;
    const int lane  = tid & 31;
    const int warpM = (wid & 1) * 64;
    const int warpN = (wid >> 1) * 64;

    const char* gzA = reinterpret_cast<const char*>(g_z16) + (size_t)blockIdx.x * BM * (DIM * 2);

    uint32_t acc[4][8][2];
    #pragma unroll
    for (int i = 0; i < 4; i++)
        #pragma unroll
        for (int j = 0; j < 8; j++) { acc[i][j][0] = 0u; acc[i][j][1] = 0u; }

    auto load_chunk = [&](int c, int st) {
        uint32_t stA = sb + st * STAGE_BYTES;
        uint32_t stB = stA + CHUNK_A_BYTES;
        const char* srcA = gzA + c * 128;
        #pragma unroll
        for (int i = 0; i < 8; i++) {
            int u = tid + i * 128;
            int r = u >> 3, c16 = u & 7;
            uint32_t off = (uint32_t)(r * 128 + c16 * 16);
            cp_async16(stA + SWZ(off), srcA + (size_t)r * (DIM * 2) + c16 * 16);
        }
        #pragma unroll
        for (int i = 0; i < 8; i++) {
            int u = tid + i * 128;
            int r = u >> 3, c16 = u & 7;
            uint32_t off = (uint32_t)(r * 128 + c16 * 16);
            cp_async16(stB + SWZ(off), srcA + (size_t)r * (DIM * 2) + c16 * 16);
        }
        CP_ASYNC_COMMIT();
    };

    const int ldRow  = lane & 15;
    const int ldColB = (lane >> 4) << 4;

    auto compute_chunk = [&](int st) {
        uint32_t stA = sb + st * STAGE_BYTES;
        uint32_t stB = stA + CHUNK_A_BYTES;
        #pragma unroll
        for (int ks = 0; ks < 4; ks++) {
            uint32_t a[4][4], b[4][4];
            #pragma unroll
            for (int mb = 0; mb < 4; mb++) {
                uint32_t off = (uint32_t)((warpM + mb * 16 + ldRow) * 128 + ks * 32 + ldColB);
                ldmatrix_x4(a[mb], stA + SWZ(off));
            }
            #pragma unroll
            for (int nb = 0; nb < 4; nb++) {
                uint32_t off = (uint32_t)((warpN + nb * 16 + ldRow) * 128 + ks * 32 + ldColB);
                ldmatrix_x4(b[nb], stB + SWZ(off));
            }
            #pragma unroll
            for (int mb = 0; mb < 4; mb++)
                #pragma unroll
                for (int nb = 0; nb < 4; nb++) {
                    mma_f16(acc[mb][nb * 2 + 0], a[mb], b[nb][0], b[nb][2]);
                    mma_f16(acc[mb][nb * 2 + 1], a[mb], b[nb][1], b[nb][3]);
                }
        }
    };

    load_chunk(0, 0);
    load_chunk(1, 1);

    #pragma unroll 1
    for (int c = 0; c < CHUNKS16 - 1; c++) {
        CP_ASYNC_WAIT_1();
        __syncthreads();
        if (c + 2 < CHUNKS16) load_chunk(c + 2, (c + 2) % STAGES);
        compute_chunk(c % STAGES);
        __syncthreads();
    }
    CP_ASYNC_WAIT_0();
    __syncthreads();
    compute_chunk((CHUNKS16 - 1) % STAGES);

    float lsum = 0.0f;
    #pragma unroll
    for (int i = 0; i < 4; i++)
        #pragma unroll
        for (int j = 0; j < 8; j++)
            #pragma unroll
            for (int k = 0; k < 2; k++) {
                float2 f = __half22float2(*reinterpret_cast<const __half2*>(&acc[i][j][k]));
                lsum += __expf(10.0f * f.x) + __expf(10.0f * f.y);
            }

    #pragma unroll
    for (int off = 16; off > 0; off >>= 1)
        lsum += __shfl_xor_sync(0xFFFFFFFFu, lsum, off);

    __shared__ double wsum[4];
    if (lane == 0) wsum[wid] = (double)lsum;
    __syncthreads();
    if (tid == 0) {
        double t = wsum[0] + wsum[1] + wsum[2] + wsum[3];
        atomicAdd(&g_pos, t);

        // fused finish: last diag CTA computes the loss (bulk kernel already done)
        __threadfence();
        unsigned int prev = atomicAdd(&g_done, 1u);
        if (prev == DIAG_TILES - 1) {
            double p = atomicAdd(&g_pos, 0.0);
            double n = atomicAdd(&g_neg, 0.0);
            out[0] = (float)(-log(p / (n + p)));
        }
    }
}

// ---------------------------------------------------------------------------
extern "C" void kernel_launch(void* const* d_in, const int* in_sizes, int n_in,
                              void* d_out, int out_size) {
    const float* zi = (const float*)d_in[0];
    const float* zj = (const float*)d_in[1];
    float* out = (float*)d_out;

    cudaFuncSetAttribute(gemm8_kernel, cudaFuncAttributeMaxDynamicSharedMemorySize, SMEM_TOTAL);
    cudaFuncSetAttribute(gemm_diag_kernel, cudaFuncAttributeMaxDynamicSharedMemorySize, SMEM_TOTAL);

    norm_kernel<<<BROWS / 8, 256>>>(zi, zj);
    gemm8_kernel<<<INT8_TILES, 128, SMEM_TOTAL>>>();
    gemm_diag_kernel<<<DIAG_TILES, 128, SMEM_TOTAL>>>(out);
}

// round 12
// speedup vs baseline: 2.8181x; 2.8181x over previous
#include <cuda_runtime.h>
#include <cuda_fp16.h>
#include <cstdint>
#include <math.h>

// ---------------------------------------------------------------------------
// Problem constants
// ---------------------------------------------------------------------------
#define NROWS     8192     // rows in z_i (and z_j)
#define DIM       512      // feature dim
#define BROWS     16384    // combined B rows (zi ++ zj)

#define BM        128      // CTA tile M
#define BN        128      // CTA tile N
#define BK        64       // K chunk (fp16 elems) = 128 bytes/row
#define CHUNKS    (DIM / BK)   // 8
#define STAGES    3

#define CHUNK_A_BYTES (BM * BK * 2)          // 16384
#define CHUNK_B_BYTES (BN * BK * 2)          // 16384
#define STAGE_BYTES   (CHUNK_A_BYTES + CHUNK_B_BYTES)  // 32768
#define SMEM_TOTAL    (STAGES * STAGE_BYTES)           // 98304 -> 2 CTAs/SM

#define NEG_TILES 4096     // 64 x 64 full tiles for zi x zj
#define POS_TILES 2080     // upper triangle incl diag of 64x64 blocks (zi x zi)
#define TOTAL_TILES (NEG_TILES + POS_TILES)  // 6176

// ---------------------------------------------------------------------------
// Global scratch (allocation-free rules: __device__ globals)
// ---------------------------------------------------------------------------
__device__ __half g_z[(size_t)BROWS * DIM];   // 16 MB: rows 0..8191 zi, 8192.. zj
__device__ double g_pos;
__device__ double g_neg;
__device__ unsigned int g_done;

// ---------------------------------------------------------------------------
// PTX helpers — only sm_80-era features (PTX target is plain sm_103; no tcgen05)
// ---------------------------------------------------------------------------
__device__ __forceinline__ uint32_t smem_to_u32(const void* p) {
    uint32_t a;
    asm("{ .reg .u64 t; cvta.to.shared.u64 t, %1; cvt.u32.u64 %0, t; }" : "=r"(a) : "l"(p));
    return a;
}

#define SWZ(off) ((off) ^ (((off) >> 3) & 0x70u))   // SW128 swizzle for 128B rows

__device__ __forceinline__ void cp_async16(uint32_t dst_smem, const void* src) {
    asm volatile("cp.async.cg.shared.global [%0], [%1], 16;" :: "r"(dst_smem), "l"(src));
}
#define CP_ASYNC_COMMIT() asm volatile("cp.async.commit_group;" ::: "memory")
#define CP_ASYNC_WAIT_1() asm volatile("cp.async.wait_group 1;" ::: "memory")
#define CP_ASYNC_WAIT_0() asm volatile("cp.async.wait_group 0;" ::: "memory")

__device__ __forceinline__ void ldmatrix_x4(uint32_t* r, uint32_t addr) {
    asm volatile("ldmatrix.sync.aligned.m8n8.x4.shared.b16 {%0,%1,%2,%3}, [%4];"
                 : "=r"(r[0]), "=r"(r[1]), "=r"(r[2]), "=r"(r[3]) : "r"(addr));
}

// D = A * B^T accumulate: mma.sync m16n8k16, fp16 in, fp16 accum (2 packed regs)
__device__ __forceinline__ void mma_f16(uint32_t* c, const uint32_t* a, uint32_t b0, uint32_t b1) {
    asm volatile(
        "mma.sync.aligned.m16n8k16.row.col.f16.f16.f16.f16 "
        "{%0,%1}, {%2,%3,%4,%5}, {%6,%7}, {%0,%1};"
        : "+r"(c[0]), "+r"(c[1])
        : "r"(a[0]), "r"(a[1]), "r"(a[2]), "r"(a[3]), "r"(b0), "r"(b1));
}

// ---------------------------------------------------------------------------
// Kernel 1: L2-normalize rows into fp16 g_z. One warp per row, 4 independent
// float4 loads per lane (MLP=4). Also resets accumulators + completion counter.
// ---------------------------------------------------------------------------
__global__ __launch_bounds__(256) void norm_kernel(const float* __restrict__ zi,
                                                   const float* __restrict__ zj) {
    const int tid  = threadIdx.x;
    const int lane = tid & 31;
    const int row  = blockIdx.x * 8 + (tid >> 5);   // 2048 blocks x 8 warps
    if (blockIdx.x == 0 && tid == 0) { g_pos = 0.0; g_neg = 0.0; g_done = 0u; }

    const float* src = (row < NROWS) ? (zi + (size_t)row * DIM)
                                     : (zj + (size_t)(row - NROWS) * DIM);
    const float4* s4 = reinterpret_cast<const float4*>(src);
    float4 v[4];
    #pragma unroll
    for (int k = 0; k < 4; k++) v[k] = s4[lane + 32 * k];

    float ss = 0.0f;
    #pragma unroll
    for (int k = 0; k < 4; k++)
        ss += v[k].x * v[k].x + v[k].y * v[k].y + v[k].z * v[k].z + v[k].w * v[k].w;
    #pragma unroll
    for (int off = 16; off > 0; off >>= 1)
        ss += __shfl_xor_sync(0xFFFFFFFFu, ss, off);

    float scale = 1.0f / fmaxf(sqrtf(ss), 1e-12f);

    __half2* dst = reinterpret_cast<__half2*>(g_z + (size_t)row * DIM);
    #pragma unroll
    for (int k = 0; k < 4; k++) {
        int e = lane + 32 * k;
        dst[e * 2 + 0] = __floats2half2_rn(v[k].x * scale, v[k].y * scale);
        dst[e * 2 + 1] = __floats2half2_rn(v[k].z * scale, v[k].w * scale);
    }
}

// ---------------------------------------------------------------------------
// Kernel 2: fused GEMM (mma.sync fp16) + weighted exp-sum epilogue.
// 128x128 tiles, 4 warps (64x64 warp tile), 3-stage cp.async pipeline,
// 2 CTAs/SM, register double-buffered fragments, AND the chunk-boundary
// wait/sync/preload moved BEFORE the last kstep's MMAs so those 32 MMAs hide
// the next chunk's first LDSM latency.
// Tile decode (1-D grid, 6176 tiles):
//   idx < 4096 : neg tile: tm = idx&63, B rows = NROWS + (idx>>6)*128, w=1
//   idx >= 4096: pos tile p -> lower-tri (t,i), i<=t: tm=i, B rows = t*128,
//                w = (i==t) ? 1 : 2   (symmetry of zi x zi^T)
// Last CTA computes the final loss (fused finish).
// ---------------------------------------------------------------------------
__global__ __launch_bounds__(128, 2) void gemm_kernel(float* __restrict__ out) {
    extern __shared__ __align__(1024) char smem[];
    const uint32_t sb = smem_to_u32(smem);
    const int tid   = threadIdx.x;
    const int wid   = tid >> 5;
    const int lane  = tid & 31;
    const int warpM = (wid & 1) * 64;
    const int warpN = (wid >> 1) * 64;

    // ---- tile decode ----
    int tm, rowB;
    float wtile;
    bool is_pos;
    {
        int idx = blockIdx.x;
        if (idx < NEG_TILES) {
            tm    = idx & 63;
            rowB  = NROWS + (idx >> 6) * BN;
            wtile = 1.0f;
            is_pos = false;
        } else {
            int p = idx - NEG_TILES;                    // 0 .. 2079
            int t = (int)((sqrtf((float)(8 * p + 1)) - 1.0f) * 0.5f);
            while ((t + 1) * (t + 2) / 2 <= p) t++;
            while (t * (t + 1) / 2 > p) t--;
            int i = p - t * (t + 1) / 2;                // 0 .. t
            tm    = i;
            rowB  = t * BN;
            wtile = (i == t) ? 1.0f : 2.0f;
            is_pos = true;
        }
    }

    const char* gzA = reinterpret_cast<const char*>(g_z) + (size_t)tm * BM * (DIM * 2);
    const char* gzB = reinterpret_cast<const char*>(g_z) + (size_t)rowB * (DIM * 2);

    uint32_t acc[4][8][2];    // fp16x2 accumulators: 64 regs
    #pragma unroll
    for (int i = 0; i < 4; i++)
        #pragma unroll
        for (int j = 0; j < 8; j++) { acc[i][j][0] = 0u; acc[i][j][1] = 0u; }

    // -------- chunk loader: 16 x cp.async(16B) per thread (A 8 + B 8) --------
    auto load_chunk = [&](int c, int st) {
        uint32_t stA = sb + st * STAGE_BYTES;
        uint32_t stB = stA + CHUNK_A_BYTES;
        const char* srcA = gzA + c * (BK * 2);   // 128 bytes of K
        const char* srcB = gzB + c * (BK * 2);
        #pragma unroll
        for (int i = 0; i < 8; i++) {            // A: 1024 16B units / 128 thr
            int u = tid + i * 128;
            int r = u >> 3, c16 = u & 7;
            uint32_t off = (uint32_t)(r * 128 + c16 * 16);
            cp_async16(stA + SWZ(off), srcA + (size_t)r * (DIM * 2) + c16 * 16);
        }
        #pragma unroll
        for (int i = 0; i < 8; i++) {            // B: 1024 16B units / 128 thr
            int u = tid + i * 128;
            int r = u >> 3, c16 = u & 7;
            uint32_t off = (uint32_t)(r * 128 + c16 * 16);
            cp_async16(stB + SWZ(off), srcB + (size_t)r * (DIM * 2) + c16 * 16);
        }
        CP_ASYNC_COMMIT();
    };

    // -------- double-buffered fragment registers --------
    uint32_t af[2][4][4], bf[2][4][4];     // 64 regs

    const int ldRow  = lane & 15;          // row within 16-row ldmatrix block
    const int ldColB = (lane >> 4) << 4;   // 0 or 16 bytes

    // load all 8 fragments of (stage st, kstep ks) into buffer buf
    auto preload = [&](int st, int ks, int buf) {
        uint32_t stA = sb + st * STAGE_BYTES;
        uint32_t stB = stA + CHUNK_A_BYTES;
        #pragma unroll
        for (int mb = 0; mb < 4; mb++) {
            uint32_t off = (uint32_t)((warpM + mb * 16 + ldRow) * 128 + ks * 32 + ldColB);
            ldmatrix_x4(af[buf][mb], stA + SWZ(off));
        }
        #pragma unroll
        for (int nb = 0; nb < 4; nb++) {
            uint32_t off = (uint32_t)((warpN + nb * 16 + ldRow) * 128 + ks * 32 + ldColB);
            ldmatrix_x4(bf[buf][nb], stB + SWZ(off));
        }
    };

    // 32 MMAs consuming buffer buf
    auto mma_all = [&](int buf) {
        #pragma unroll
        for (int mb = 0; mb < 4; mb++)
            #pragma unroll
            for (int nb = 0; nb < 4; nb++) {
                mma_f16(acc[mb][nb * 2 + 0], af[buf][mb], bf[buf][nb][0], bf[buf][nb][2]);
                mma_f16(acc[mb][nb * 2 + 1], af[buf][mb], bf[buf][nb][1], bf[buf][nb][3]);
            }
    };

    // -------- prologue: fill stages, preload first fragments --------
    load_chunk(0, 0);
    load_chunk(1, 1);
    CP_ASYNC_WAIT_1();      // chunk 0 resident
    __syncthreads();
    preload(0, 0, 0);

    int cur = 0;
    #pragma unroll 1
    for (int c = 0; c < CHUNKS; c++) {
        const int st = c % STAGES;
        if (c + 2 < CHUNKS) load_chunk(c + 2, (c + 2) % STAGES);

        #pragma unroll
        for (int ks = 0; ks < 4; ks++) {
            if (ks < 3) {
                preload(st, ks + 1, cur ^ 1);          // hide LDSM under MMAs
            } else if (c + 1 < CHUNKS) {
                // chunk boundary INSIDE the last kstep: wait for next chunk's
                // data, sync (stage-reuse guard: all reads of stage st done at
                // ks=2's preload), then preload next chunk's kstep 0 so the
                // following 32 MMAs hide its LDSM latency.
                if (c + 2 < CHUNKS) CP_ASYNC_WAIT_1();
                else                CP_ASYNC_WAIT_0();
                __syncthreads();
                preload((c + 1) % STAGES, 0, cur ^ 1);
            }
            mma_all(cur);
            cur ^= 1;
        }
    }

    // -------- epilogue: weighted sum of exp(10 * acc) --------
    float lsum = 0.0f;
    #pragma unroll
    for (int i = 0; i < 4; i++)
        #pragma unroll
        for (int j = 0; j < 8; j++)
            #pragma unroll
            for (int k = 0; k < 2; k++) {
                float2 f = __half22float2(*reinterpret_cast<const __half2*>(&acc[i][j][k]));
                lsum += __expf(10.0f * f.x) + __expf(10.0f * f.y);
            }
    lsum *= wtile;

    #pragma unroll
    for (int off = 16; off > 0; off >>= 1)
        lsum += __shfl_xor_sync(0xFFFFFFFFu, lsum, off);

    __shared__ double wsum[4];
    if (lane == 0) wsum[wid] = (double)lsum;
    __syncthreads();
    if (tid == 0) {
        double t = wsum[0] + wsum[1] + wsum[2] + wsum[3];
        atomicAdd(is_pos ? &g_pos : &g_neg, t);

        // fused finish: last CTA to complete computes the loss
        __threadfence();
        unsigned int prev = atomicAdd(&g_done, 1u);
        if (prev == TOTAL_TILES - 1) {
            double p = atomicAdd(&g_pos, 0.0);
            double n = atomicAdd(&g_neg, 0.0);
            out[0] = (float)(-log(p / (n + p)));
        }
    }
}

// ---------------------------------------------------------------------------
extern "C" void kernel_launch(void* const* d_in, const int* in_sizes, int n_in,
                              void* d_out, int out_size) {
    const float* zi = (const float*)d_in[0];
    const float* zj = (const float*)d_in[1];
    float* out = (float*)d_out;

    cudaFuncSetAttribute(gemm_kernel, cudaFuncAttributeMaxDynamicSharedMemorySize, SMEM_TOTAL);

    norm_kernel<<<BROWS / 8, 256>>>(zi, zj);
    gemm_kernel<<<TOTAL_TILES, 128, SMEM_TOTAL>>>(out);
}

// round 13
// speedup vs baseline: 2.9343x; 1.0412x over previous
#include <cuda_runtime.h>
#include <cuda_fp16.h>
#include <cstdint>
#include <math.h>

// ---------------------------------------------------------------------------
// Problem constants
// ---------------------------------------------------------------------------
#define NROWS     8192     // rows in z_i (and z_j)
#define DIM       512      // feature dim
#define BROWS     16384    // combined B rows (zi ++ zj)

#define BM        128      // CTA tile M
#define BN        128      // CTA tile N
#define BK        64       // K chunk (fp16 elems) = 128 bytes/row
#define CHUNKS    (DIM / BK)   // 8
#define STAGES    3

#define CHUNK_A_BYTES (BM * BK * 2)          // 16384
#define CHUNK_B_BYTES (BN * BK * 2)          // 16384
#define STAGE_BYTES   (CHUNK_A_BYTES + CHUNK_B_BYTES)  // 32768
#define SMEM_TOTAL    (STAGES * STAGE_BYTES)           // 98304 -> 2 CTAs/SM

#define NEG_TILES 4096     // 64 x 64 full tiles for zi x zj
#define POS_TILES 2080     // upper triangle incl diag of 64x64 blocks (zi x zi)
#define TOTAL_TILES (NEG_TILES + POS_TILES)  // 6176

// ---------------------------------------------------------------------------
// Global scratch (allocation-free rules: __device__ globals)
// ---------------------------------------------------------------------------
__device__ __half g_z[(size_t)BROWS * DIM];   // 16 MB: rows 0..8191 zi, 8192.. zj
__device__ double g_pos;
__device__ double g_neg;
__device__ unsigned int g_done;

// ---------------------------------------------------------------------------
// PTX helpers — only sm_80-era features (PTX target is plain sm_103; no tcgen05)
// ---------------------------------------------------------------------------
__device__ __forceinline__ uint32_t smem_to_u32(const void* p) {
    uint32_t a;
    asm("{ .reg .u64 t; cvta.to.shared.u64 t, %1; cvt.u32.u64 %0, t; }" : "=r"(a) : "l"(p));
    return a;
}

#define SWZ(off) ((off) ^ (((off) >> 3) & 0x70u))   // SW128 swizzle for 128B rows

__device__ __forceinline__ void cp_async16(uint32_t dst_smem, const void* src) {
    asm volatile("cp.async.cg.shared.global [%0], [%1], 16;" :: "r"(dst_smem), "l"(src));
}
#define CP_ASYNC_COMMIT() asm volatile("cp.async.commit_group;" ::: "memory")
#define CP_ASYNC_WAIT_1() asm volatile("cp.async.wait_group 1;" ::: "memory")
#define CP_ASYNC_WAIT_0() asm volatile("cp.async.wait_group 0;" ::: "memory")

__device__ __forceinline__ void ldmatrix_x4(uint32_t* r, uint32_t addr) {
    asm volatile("ldmatrix.sync.aligned.m8n8.x4.shared.b16 {%0,%1,%2,%3}, [%4];"
                 : "=r"(r[0]), "=r"(r[1]), "=r"(r[2]), "=r"(r[3]) : "r"(addr));
}

// D = A * B^T accumulate: mma.sync m16n8k16, fp16 in, fp16 accum (2 packed regs)
__device__ __forceinline__ void mma_f16(uint32_t* c, const uint32_t* a, uint32_t b0, uint32_t b1) {
    asm volatile(
        "mma.sync.aligned.m16n8k16.row.col.f16.f16.f16.f16 "
        "{%0,%1}, {%2,%3,%4,%5}, {%6,%7}, {%0,%1};"
        : "+r"(c[0]), "+r"(c[1])
        : "r"(a[0]), "r"(a[1]), "r"(a[2]), "r"(a[3]), "r"(b0), "r"(b1));
}

// ---------------------------------------------------------------------------
// Kernel 1: L2-normalize rows into fp16 g_z. One warp per row, 4 independent
// float4 loads per lane (MLP=4). Also resets accumulators + completion counter.
// ---------------------------------------------------------------------------
__global__ __launch_bounds__(256) void norm_kernel(const float* __restrict__ zi,
                                                   const float* __restrict__ zj) {
    const int tid  = threadIdx.x;
    const int lane = tid & 31;
    const int row  = blockIdx.x * 8 + (tid >> 5);   // 2048 blocks x 8 warps
    if (blockIdx.x == 0 && tid == 0) { g_pos = 0.0; g_neg = 0.0; g_done = 0u; }

    const float* src = (row < NROWS) ? (zi + (size_t)row * DIM)
                                     : (zj + (size_t)(row - NROWS) * DIM);
    const float4* s4 = reinterpret_cast<const float4*>(src);
    float4 v[4];
    #pragma unroll
    for (int k = 0; k < 4; k++) v[k] = s4[lane + 32 * k];

    float ss = 0.0f;
    #pragma unroll
    for (int k = 0; k < 4; k++)
        ss += v[k].x * v[k].x + v[k].y * v[k].y + v[k].z * v[k].z + v[k].w * v[k].w;
    #pragma unroll
    for (int off = 16; off > 0; off >>= 1)
        ss += __shfl_xor_sync(0xFFFFFFFFu, ss, off);

    float scale = 1.0f / fmaxf(sqrtf(ss), 1e-12f);

    __half2* dst = reinterpret_cast<__half2*>(g_z + (size_t)row * DIM);
    #pragma unroll
    for (int k = 0; k < 4; k++) {
        int e = lane + 32 * k;
        dst[e * 2 + 0] = __floats2half2_rn(v[k].x * scale, v[k].y * scale);
        dst[e * 2 + 1] = __floats2half2_rn(v[k].z * scale, v[k].w * scale);
    }
}

// ---------------------------------------------------------------------------
// Kernel 2: fused GEMM (mma.sync fp16) + weighted exp-sum epilogue.
// 128x128 tiles, 4 warps (64x64 warp tile), 3-stage cp.async pipeline,
// 2 CTAs/SM, register double-buffered fragments with FINE-GRAINED interleave:
//   - preload split into A/B halves interleaved with 16-MMA half-bursts
//   - next-next chunk's 16 cp.asyncs spread 4-per-kstep (commit at ks3)
// Tile decode (1-D grid, 6176 tiles):
//   idx < 4096 : neg tile: tm = idx&63, B rows = NROWS + (idx>>6)*128, w=1
//   idx >= 4096: pos tile p -> lower-tri (t,i), i<=t: tm=i, B rows = t*128,
//                w = (i==t) ? 1 : 2   (symmetry of zi x zi^T)
// Last CTA computes the final loss (fused finish).
// ---------------------------------------------------------------------------
__global__ __launch_bounds__(128, 2) void gemm_kernel(float* __restrict__ out) {
    extern __shared__ __align__(1024) char smem[];
    const uint32_t sb = smem_to_u32(smem);
    const int tid   = threadIdx.x;
    const int wid   = tid >> 5;
    const int lane  = tid & 31;
    const int warpM = (wid & 1) * 64;
    const int warpN = (wid >> 1) * 64;

    // ---- tile decode ----
    int tm, rowB;
    float wtile;
    bool is_pos;
    {
        int idx = blockIdx.x;
        if (idx < NEG_TILES) {
            tm    = idx & 63;
            rowB  = NROWS + (idx >> 6) * BN;
            wtile = 1.0f;
            is_pos = false;
        } else {
            int p = idx - NEG_TILES;                    // 0 .. 2079
            int t = (int)((sqrtf((float)(8 * p + 1)) - 1.0f) * 0.5f);
            while ((t + 1) * (t + 2) / 2 <= p) t++;
            while (t * (t + 1) / 2 > p) t--;
            int i = p - t * (t + 1) / 2;                // 0 .. t
            tm    = i;
            rowB  = t * BN;
            wtile = (i == t) ? 1.0f : 2.0f;
            is_pos = true;
        }
    }

    const char* gzA = reinterpret_cast<const char*>(g_z) + (size_t)tm * BM * (DIM * 2);
    const char* gzB = reinterpret_cast<const char*>(g_z) + (size_t)rowB * (DIM * 2);

    uint32_t acc[4][8][2];    // fp16x2 accumulators: 64 regs
    #pragma unroll
    for (int i = 0; i < 4; i++)
        #pragma unroll
        for (int j = 0; j < 8; j++) { acc[i][j][0] = 0u; acc[i][j][1] = 0u; }

    // -------- chunk loader (full, prologue only): 16 x cp.async(16B) --------
    auto load_chunk = [&](int c, int st) {
        uint32_t stA = sb + st * STAGE_BYTES;
        uint32_t stB = stA + CHUNK_A_BYTES;
        const char* srcA = gzA + c * (BK * 2);
        const char* srcB = gzB + c * (BK * 2);
        #pragma unroll
        for (int i = 0; i < 8; i++) {
            int u = tid + i * 128;
            int r = u >> 3, c16 = u & 7;
            uint32_t off = (uint32_t)(r * 128 + c16 * 16);
            cp_async16(stA + SWZ(off), srcA + (size_t)r * (DIM * 2) + c16 * 16);
        }
        #pragma unroll
        for (int i = 0; i < 8; i++) {
            int u = tid + i * 128;
            int r = u >> 3, c16 = u & 7;
            uint32_t off = (uint32_t)(r * 128 + c16 * 16);
            cp_async16(stB + SWZ(off), srcB + (size_t)r * (DIM * 2) + c16 * 16);
        }
        CP_ASYNC_COMMIT();
    };

    // partial loader: 4 of 16 cp.asyncs (part 0..3); A on parts 0-1, B on 2-3
    auto load_chunk_part = [&](int c, int st, int part) {
        uint32_t stA = sb + st * STAGE_BYTES;
        uint32_t stB = stA + CHUNK_A_BYTES;
        const char* srcA = gzA + c * (BK * 2);
        const char* srcB = gzB + c * (BK * 2);
        if (part < 2) {
            #pragma unroll
            for (int i = 0; i < 4; i++) {
                int u = tid + (part * 4 + i) * 128;
                int r = u >> 3, c16 = u & 7;
                uint32_t off = (uint32_t)(r * 128 + c16 * 16);
                cp_async16(stA + SWZ(off), srcA + (size_t)r * (DIM * 2) + c16 * 16);
            }
        } else {
            #pragma unroll
            for (int i = 0; i < 4; i++) {
                int u = tid + ((part - 2) * 4 + i) * 128;
                int r = u >> 3, c16 = u & 7;
                uint32_t off = (uint32_t)(r * 128 + c16 * 16);
                cp_async16(stB + SWZ(off), srcB + (size_t)r * (DIM * 2) + c16 * 16);
            }
        }
        if (part == 3) CP_ASYNC_COMMIT();
    };

    // -------- double-buffered fragment registers --------
    uint32_t af[2][4][4], bf[2][4][4];     // 64 regs

    const int ldRow  = lane & 15;
    const int ldColB = (lane >> 4) << 4;

    auto preload_A = [&](int st, int ks, int buf) {
        uint32_t stA = sb + st * STAGE_BYTES;
        #pragma unroll
        for (int mb = 0; mb < 4; mb++) {
            uint32_t off = (uint32_t)((warpM + mb * 16 + ldRow) * 128 + ks * 32 + ldColB);
            ldmatrix_x4(af[buf][mb], stA + SWZ(off));
        }
    };
    auto preload_B = [&](int st, int ks, int buf) {
        uint32_t stB = sb + st * STAGE_BYTES + CHUNK_A_BYTES;
        #pragma unroll
        for (int nb = 0; nb < 4; nb++) {
            uint32_t off = (uint32_t)((warpN + nb * 16 + ldRow) * 128 + ks * 32 + ldColB);
            ldmatrix_x4(bf[buf][nb], stB + SWZ(off));
        }
    };

    // 16 MMAs: mBlocks [mb0, mb0+2) x all 8 n-fragments of buffer buf
    auto mma_half = [&](int buf, int mb0) {
        #pragma unroll
        for (int mb = mb0; mb < mb0 + 2; mb++)
            #pragma unroll
            for (int nb = 0; nb < 4; nb++) {
                mma_f16(acc[mb][nb * 2 + 0], af[buf][mb], bf[buf][nb][0], bf[buf][nb][2]);
                mma_f16(acc[mb][nb * 2 + 1], af[buf][mb], bf[buf][nb][1], bf[buf][nb][3]);
            }
    };

    // -------- prologue: fill stages, preload first fragments --------
    load_chunk(0, 0);
    load_chunk(1, 1);
    CP_ASYNC_WAIT_1();      // chunk 0 resident
    __syncthreads();
    preload_A(0, 0, 0);
    preload_B(0, 0, 0);

    int cur = 0;
    #pragma unroll 1
    for (int c = 0; c < CHUNKS; c++) {
        const int st = c % STAGES;
        const bool have_next2 = (c + 2 < CHUNKS);

        #pragma unroll
        for (int ks = 0; ks < 4; ks++) {
            if (have_next2) load_chunk_part(c + 2, (c + 2) % STAGES, ks);

            if (ks < 3) {
                // interleave: B-LDSM, 16 MMA, A-LDSM, 16 MMA
                preload_B(st, ks + 1, cur ^ 1);
                mma_half(cur, 0);
                preload_A(st, ks + 1, cur ^ 1);
                mma_half(cur, 2);
            } else if (c + 1 < CHUNKS) {
                // chunk boundary inside last kstep: wait next chunk, sync
                // (stage-reuse guard: all reads of stage st issued by ks=2's
                // preload and fenced by this barrier), preload next kstep 0.
                if (have_next2) CP_ASYNC_WAIT_1();
                else            CP_ASYNC_WAIT_0();
                __syncthreads();
                preload_B((c + 1) % STAGES, 0, cur ^ 1);
                mma_half(cur, 0);
                preload_A((c + 1) % STAGES, 0, cur ^ 1);
                mma_half(cur, 2);
            } else {
                mma_half(cur, 0);
                mma_half(cur, 2);
            }
            cur ^= 1;
        }
    }

    // -------- epilogue: weighted sum of exp(10 * acc) --------
    float lsum = 0.0f;
    #pragma unroll
    for (int i = 0; i < 4; i++)
        #pragma unroll
        for (int j = 0; j < 8; j++)
            #pragma unroll
            for (int k = 0; k < 2; k++) {
                float2 f = __half22float2(*reinterpret_cast<const __half2*>(&acc[i][j][k]));
                lsum += __expf(10.0f * f.x) + __expf(10.0f * f.y);
            }
    lsum *= wtile;

    #pragma unroll
    for (int off = 16; off > 0; off >>= 1)
        lsum += __shfl_xor_sync(0xFFFFFFFFu, lsum, off);

    __shared__ double wsum[4];
    if (lane == 0) wsum[wid] = (double)lsum;
    __syncthreads();
    if (tid == 0) {
        double t = wsum[0] + wsum[1] + wsum[2] + wsum[3];
        atomicAdd(is_pos ? &g_pos : &g_neg, t);

        // fused finish: last CTA to complete computes the loss
        __threadfence();
        unsigned int prev = atomicAdd(&g_done, 1u);
        if (prev == TOTAL_TILES - 1) {
            double p = atomicAdd(&g_pos, 0.0);
            double n = atomicAdd(&g_neg, 0.0);
            out[0] = (float)(-log(p / (n + p)));
        }
    }
}

// ---------------------------------------------------------------------------
extern "C" void kernel_launch(void* const* d_in, const int* in_sizes, int n_in,
                              void* d_out, int out_size) {
    const float* zi = (const float*)d_in[0];
    const float* zj = (const float*)d_in[1];
    float* out = (float*)d_out;

    cudaFuncSetAttribute(gemm_kernel, cudaFuncAttributeMaxDynamicSharedMemorySize, SMEM_TOTAL);

    norm_kernel<<<BROWS / 8, 256>>>(zi, zj);
    gemm_kernel<<<TOTAL_TILES, 128, SMEM_TOTAL>>>(out);
}